// round 14
// baseline (speedup 1.0000x reference)
#include <cuda_runtime.h>
#include <stdint.h>

// Problem constants
#define BSZ  16
#define SEQN 1024
#define NVV  512
#define DMM  256
#define KCL  8

// Tiling: block = 16 v x 256 d x full K, 256 threads, 2 blocks/SM co-res.
// grid = 512 (16 b x 32 v-chunks) -> 1.73 waves, HW work-stealing balance.
#define VT 16
#define KB 16
#define NCH (SEQN / KB)       // 64
#define NSTG 3                // cp.async pipeline stages
#define APAD 36               // As row stride (floats), 144B
#define BPAD 264              // Bs row stride (floats), 1056B

#define AS_SZ (NSTG * KB * APAD)        // 1728 floats
#define BS_SZ (NSTG * KB * BPAD)        // 12672 floats
#define SMEM_BYTES ((AS_SZ + BS_SZ) * 4)  // 57600 B

typedef unsigned long long ull;

// -------- device scratch ---------------------------------------------------
__device__ float g_wt[SEQN * DMM];      // W transposed: [s][d]

// -------- packed f32x2 helpers --------------------------------------------
__device__ __forceinline__ ull pack2(float x, float y) {
    ull r; asm("mov.b64 %0, {%1, %2};" : "=l"(r) : "f"(x), "f"(y)); return r;
}
__device__ __forceinline__ float2 unpk2(ull a) {
    float2 f; asm("mov.b64 {%0, %1}, %2;" : "=f"(f.x), "=f"(f.y) : "l"(a)); return f;
}
__device__ __forceinline__ void fma2(ull& d, ull a, ull b) {
    asm("fma.rn.f32x2 %0, %1, %2, %0;" : "+l"(d) : "l"(a), "l"(b));
}
__device__ __forceinline__ uint32_t smem_u32(const void* p) {
    uint32_t a;
    asm("{ .reg .u64 t; cvta.to.shared.u64 t, %1; cvt.u32.u64 %0, t; }"
        : "=r"(a) : "l"(p));
    return a;
}
#define CP16(dst, src) \
    asm volatile("cp.async.cg.shared.global [%0], [%1], 16;" \
                 :: "r"(dst), "l"(src) : "memory")
#define CP_COMMIT() asm volatile("cp.async.commit_group;" ::: "memory")

// -------- JAX threefry2x32 (key = (0,7)), partitionable 32-bit fold -------
__device__ __forceinline__ uint32_t rotl32(uint32_t x, int r) {
    return (x << r) | (x >> (32 - r));
}
__device__ __forceinline__ uint32_t threefry_bits32(uint32_t c0, uint32_t c1) {
    const uint32_t ks0 = 0u, ks1 = 7u;
    const uint32_t ks2 = ks0 ^ ks1 ^ 0x1BD11BDAu;
    uint32_t x0 = c0 + ks0, x1 = c1 + ks1;
#define TFR(r) { x0 += x1; x1 = rotl32(x1, (r)); x1 ^= x0; }
    TFR(13) TFR(15) TFR(26) TFR(6)   x0 += ks1; x1 += ks2 + 1u;
    TFR(17) TFR(29) TFR(16) TFR(24)  x0 += ks2; x1 += ks0 + 2u;
    TFR(13) TFR(15) TFR(26) TFR(6)   x0 += ks0; x1 += ks1 + 3u;
    TFR(17) TFR(29) TFR(16) TFR(24)  x0 += ks1; x1 += ks2 + 4u;
    TFR(13) TFR(15) TFR(26) TFR(6)   x0 += ks2; x1 += ks0 + 5u;
#undef TFR
    return x0 ^ x1;
}

// -------- kernel 0: transpose W -> g_wt[s][d] ------------------------------
__global__ void transpose_w(const float* __restrict__ W) {
    __shared__ float t[32][33];
    int s0 = blockIdx.x * 32, d0 = blockIdx.y * 32;
    int tx = threadIdx.x & 31, r = threadIdx.x >> 5;   // r: 0..7
#pragma unroll
    for (int i = 0; i < 4; ++i) {
        int d = r + i * 8;
        t[d][tx] = W[(size_t)(d0 + d) * SEQN + s0 + tx];
    }
    __syncthreads();
#pragma unroll
    for (int i = 0; i < 4; ++i) {
        int s = r + i * 8;
        g_wt[(size_t)(s0 + s) * DMM + d0 + tx] = t[tx][s];
    }
}

// -------- fused kernel -----------------------------------------------------
// 256 threads / 8 warps. Block: 16v x 256d x K=1024, cp.async 3-stage.
// Warp tile: 16v x 32d. Thread: 2v x 8d (vl=lane&7 -> v=vl*2, dl=lane>>3).
// Inner loop per k: 1 LDS.64 (A) + 2 LDS.128 (B) + 2 pack + 8 FFMA2.
__global__ __launch_bounds__(256, 2)
void fused_kernel(const float* __restrict__ x, const float* __restrict__ bias,
                  const float* __restrict__ ce, float4* __restrict__ out) {
    extern __shared__ float smem[];
    float* As = smem;                 // [st][KB][APAD]
    float* Bs = smem + AS_SZ;         // [st][KB][BPAD]
    const uint32_t as_u = smem_u32(As);
    const uint32_t bs_u = smem_u32(Bs);

    const int bid = blockIdx.x;
    const int vc  = bid & 31;
    const int b   = bid >> 5;
    const int v0  = vc * VT;

    const int tid  = threadIdx.x;
    const int w    = tid >> 5;
    const int lane = tid & 31;
    const int vl   = lane & 7;            // v = vl*2
    const int dl   = lane >> 3;           // d = w*32 + dl*8
    const int dloc = w * 32 + dl * 8;

    const float* xb = x + ((size_t)b * SEQN) * NVV + v0;

    ull c2[2][4];
#pragma unroll
    for (int i = 0; i < 2; ++i)
#pragma unroll
        for (int q = 0; q < 4; ++q) c2[i][q] = 0ull;

    // ---- cp.async chunk issue ----
    // x: threads 0..63, one 16B each: k=tid>>2, q=tid&3
    // W: all 256, four 16B each from g_wt rows
    auto issue = [&](int c, int st) {
        int s0 = c * KB;
        if (tid < 64) {
            int k = tid >> 2, q = tid & 3;
            CP16(as_u + (uint32_t)(((st * KB + k) * APAD + q * 4) * 4),
                 xb + (size_t)(s0 + k) * NVV + q * 4);
        }
#pragma unroll
        for (int i = 0; i < 4; ++i) {
            int e = i * 256 + tid;
            int k = e >> 6, q = e & 63;
            CP16(bs_u + (uint32_t)(((st * KB + k) * BPAD + q * 4) * 4),
                 &g_wt[(size_t)(s0 + k) * DMM + q * 4]);
        }
        CP_COMMIT();
    };

    issue(0, 0);
    issue(1, 1);

    for (int c = 0; c < NCH; ++c) {
        if (c < NCH - 1)
            asm volatile("cp.async.wait_group 1;" ::: "memory");
        else
            asm volatile("cp.async.wait_group 0;" ::: "memory");
        __syncthreads();
        if (c + 2 < NCH) {
            int nc = c + 2;
            int st = nc % NSTG;
            issue(nc, st);
        }
        const float* ap = As + (size_t)(c % NSTG) * KB * APAD;
        const float* bp = Bs + (size_t)(c % NSTG) * KB * BPAD;
#pragma unroll
        for (int k = 0; k < KB; ++k) {
            float2 af = *(const float2*)&ap[k * APAD + vl * 2];
            ulonglong2 b01 = *(const ulonglong2*)&bp[k * BPAD + dloc];
            ulonglong2 b23 = *(const ulonglong2*)&bp[k * BPAD + dloc + 4];
            ull a0 = pack2(af.x, af.x);
            ull a1 = pack2(af.y, af.y);
            fma2(c2[0][0], a0, b01.x); fma2(c2[0][1], a0, b01.y);
            fma2(c2[0][2], a0, b23.x); fma2(c2[0][3], a0, b23.y);
            fma2(c2[1][0], a1, b01.x); fma2(c2[1][1], a1, b01.y);
            fma2(c2[1][2], a1, b23.x); fma2(c2[1][3], a1, b23.y);
        }
    }

    // ---- epilogue: cn norm + bias + cosine + sinkhorn ----
    __syncthreads();
    float* cn_s   = smem;                  // [8][256]
    float* bias_s = smem + 2048;           // [256]
    float* red    = smem + 2304;           // [8 warps][16 v][9] = 1152
    float* soft_s = smem + 3456;           // [16][8]
    float* bvals  = smem + 3584;           // [128]

    {   // warp w normalizes cn row w (full 256 d)
        const float* row = ce + w * DMM;
        float s = 0.f;
#pragma unroll
        for (int q = 0; q < DMM / 32; ++q) {
            float t = row[lane + q * 32];
            s += t * t;
        }
#pragma unroll
        for (int o = 16; o; o >>= 1) s += __shfl_xor_sync(0xffffffffu, s, o);
        float nrm = fmaxf(sqrtf(s), 1e-12f);
#pragma unroll
        for (int q = 0; q < DMM / 32; ++q)
            cn_s[w * DMM + lane + q * 32] = row[lane + q * 32] / nrm;
    }
    bias_s[tid] = bias[tid];
    __syncthreads();

#pragma unroll
    for (int vi = 0; vi < 2; ++vi) {      // 2 v per thread
        float y[8];
#pragma unroll
        for (int q = 0; q < 4; ++q) {
            float2 p = unpk2(c2[vi][q]);
            y[2 * q]     = p.x + bias_s[dloc + 2 * q];
            y[2 * q + 1] = p.y + bias_s[dloc + 2 * q + 1];
        }
        float r[9];
        r[0] = 0.f;
#pragma unroll
        for (int q = 0; q < 8; ++q) r[0] += y[q] * y[q];
#pragma unroll
        for (int kk = 0; kk < KCL; ++kk) {
            const float* cp = &cn_s[kk * DMM + dloc];
            float s = 0.f;
#pragma unroll
            for (int q = 0; q < 8; ++q) s += y[q] * cp[q];
            r[1 + kk] = s;
        }
        // reduce across dl (lane bits 3,4)
#pragma unroll
        for (int o = 8; o <= 16; o <<= 1) {
#pragma unroll
            for (int q = 0; q < 9; ++q)
                r[q] += __shfl_xor_sync(0xffffffffu, r[q], o);
        }
        if (dl == 0) {      // lanes 0..7: vl == lane
            float* dst = red + ((size_t)w * VT + lane * 2 + vi) * 9;
#pragma unroll
            for (int q = 0; q < 9; ++q) dst[q] = r[q];
        }
    }
    __syncthreads();

    if (tid < VT) {         // sum across 8 warps -> sinkhorn
        float acc[9];
#pragma unroll
        for (int q = 0; q < 9; ++q) acc[q] = 0.f;
#pragma unroll
        for (int ww = 0; ww < 8; ++ww) {
            const float* src = red + ((size_t)ww * VT + tid) * 9;
#pragma unroll
            for (int q = 0; q < 9; ++q) acc[q] += src[q];
        }
        float nrm = fmaxf(sqrtf(acc[0]), 1e-12f);
        float e[KCL], esum = 0.f;
#pragma unroll
        for (int kk = 0; kk < KCL; ++kk) {
            float prob = acc[1 + kk] / nrm;
            e[kk] = expf(prob / 0.05f);
            esum += e[kk];
        }
#pragma unroll
        for (int kk = 0; kk < KCL; ++kk) soft_s[tid * KCL + kk] = e[kk] / esum;
    }
    __syncthreads();

    if (tid < 128) {        // bern: one thread per (kk, v) = 8*16
        int kk = tid >> 4, v = tid & 15;
        int r = kk * (BSZ * NVV) + b * NVV + v0 + v;
        uint32_t bits = threefry_bits32(0u, (uint32_t)r);
        float f = __uint_as_float((bits >> 9) | 0x3f800000u) - 1.0f;
        float u = fmaxf(0.0f, f);
        bvals[tid] = (u < soft_s[v * KCL + kk]) ? 1.0f : 0.0f;
    }
    __syncthreads();

    // ---- write this block's 128 output rows (512 KB) ----
#pragma unroll
    for (int kk = 0; kk < KCL; ++kk) {
        size_t base = (size_t)kk * (BSZ * NVV) + b * NVV + v0;
#pragma unroll
        for (int rr = 0; rr < VT; ++rr) {
            float v = bvals[kk * VT + rr];
            __stcs(&out[(base + rr) * 256 + tid], make_float4(v, v, v, v));
        }
    }
}

// -------- launch -----------------------------------------------------------
extern "C" void kernel_launch(void* const* d_in, const int* in_sizes, int n_in,
                              void* d_out, int out_size) {
    const float* x = nullptr;
    const float* W = nullptr;
    const float* bias = nullptr;
    const float* ce = nullptr;
    for (int i = 0; i < n_in; ++i) {
        switch (in_sizes[i]) {
            case BSZ * SEQN * NVV: x    = (const float*)d_in[i]; break;
            case DMM * SEQN:       W    = (const float*)d_in[i]; break;
            case DMM:              bias = (const float*)d_in[i]; break;
            case KCL * DMM:        ce   = (const float*)d_in[i]; break;
            default: break;
        }
    }
    float4* out = (float4*)d_out;

    static bool attr_set = false;
    if (!attr_set) {
        cudaFuncSetAttribute(fused_kernel,
                             cudaFuncAttributeMaxDynamicSharedMemorySize,
                             SMEM_BYTES);
        attr_set = true;
    }

    transpose_w<<<dim3(SEQN / 32, DMM / 32), 256>>>(W);
    fused_kernel<<<512, 256, SMEM_BYTES>>>(x, bias, ce, out);
    (void)out_size;
}

// round 15
// speedup vs baseline: 1.3054x; 1.3054x over previous
#include <cuda_runtime.h>
#include <stdint.h>

// Problem constants
#define BSZ  16
#define SEQN 1024
#define NVV  512
#define DMM  256
#define KCL  8

// Tiling: block = 32 v x 256 d x full K, 256 threads, 2 blocks/SM.
// grid = 16 b x 16 vc = 256 blocks.
#define VT 32
#define KB 16
#define NCH (SEQN / KB)       // 64
#define NSTG 3
#define APAD 36               // As row stride (floats): 144B
#define BPAD 264              // Bs row stride (floats): 1056B

#define AS_SZ (NSTG * KB * APAD)          // 1728 floats
#define BS_SZ (NSTG * KB * BPAD)          // 12672 floats
#define SMEM_BYTES ((AS_SZ + BS_SZ) * 4)  // 57600 B

typedef unsigned long long ull;

// -------- device scratch ---------------------------------------------------
__device__ float g_wt[SEQN * DMM];      // W transposed: [s][d]

// -------- packed f32x2 helpers --------------------------------------------
__device__ __forceinline__ ull pack2(float x, float y) {
    ull r; asm("mov.b64 %0, {%1, %2};" : "=l"(r) : "f"(x), "f"(y)); return r;
}
__device__ __forceinline__ float2 unpk2(ull a) {
    float2 f; asm("mov.b64 {%0, %1}, %2;" : "=f"(f.x), "=f"(f.y) : "l"(a)); return f;
}
__device__ __forceinline__ void fma2(ull& d, ull a, ull b) {
    asm("fma.rn.f32x2 %0, %1, %2, %0;" : "+l"(d) : "l"(a), "l"(b));
}
__device__ __forceinline__ uint32_t smem_u32(const void* p) {
    uint32_t a;
    asm("{ .reg .u64 t; cvta.to.shared.u64 t, %1; cvt.u32.u64 %0, t; }"
        : "=r"(a) : "l"(p));
    return a;
}
#define CP16(dst, src) \
    asm volatile("cp.async.cg.shared.global [%0], [%1], 16;" \
                 :: "r"(dst), "l"(src) : "memory")
#define CP_COMMIT() asm volatile("cp.async.commit_group;" ::: "memory")

// -------- JAX threefry2x32 (key = (0,7)), partitionable 32-bit fold -------
__device__ __forceinline__ uint32_t rotl32(uint32_t x, int r) {
    return (x << r) | (x >> (32 - r));
}
__device__ __forceinline__ uint32_t threefry_bits32(uint32_t c0, uint32_t c1) {
    const uint32_t ks0 = 0u, ks1 = 7u;
    const uint32_t ks2 = ks0 ^ ks1 ^ 0x1BD11BDAu;
    uint32_t x0 = c0 + ks0, x1 = c1 + ks1;
#define TFR(r) { x0 += x1; x1 = rotl32(x1, (r)); x1 ^= x0; }
    TFR(13) TFR(15) TFR(26) TFR(6)   x0 += ks1; x1 += ks2 + 1u;
    TFR(17) TFR(29) TFR(16) TFR(24)  x0 += ks2; x1 += ks0 + 2u;
    TFR(13) TFR(15) TFR(26) TFR(6)   x0 += ks0; x1 += ks1 + 3u;
    TFR(17) TFR(29) TFR(16) TFR(24)  x0 += ks1; x1 += ks2 + 4u;
    TFR(13) TFR(15) TFR(26) TFR(6)   x0 += ks2; x1 += ks0 + 5u;
#undef TFR
    return x0 ^ x1;
}

// -------- kernel 0: transpose W -> g_wt[s][d] ------------------------------
__global__ void transpose_w(const float* __restrict__ W) {
    __shared__ float t[32][33];
    int s0 = blockIdx.x * 32, d0 = blockIdx.y * 32;
    int tx = threadIdx.x & 31, r = threadIdx.x >> 5;
#pragma unroll
    for (int i = 0; i < 4; ++i) {
        int d = r + i * 8;
        t[d][tx] = W[(size_t)(d0 + d) * SEQN + s0 + tx];
    }
    __syncthreads();
#pragma unroll
    for (int i = 0; i < 4; ++i) {
        int s = r + i * 8;
        g_wt[(size_t)(s0 + s) * DMM + d0 + tx] = t[tx][s];
    }
}

// -------- fused kernel -----------------------------------------------------
// 256 threads / 8 warps / 2 blocks per SM. Block: 32v x 256d x K=1024.
// Warp tile: 32v x 32d. Thread: 4v x 8d (vl=lane&7 -> v=vl*4, dl=lane>>3).
// Inner loop per k: 1 LDS.128 (A) + 2 LDS.128 (B) + 4 pack + 16 FFMA2.
// Feed: 3-stage cp.async ring, addresses strength-reduced.
__global__ __launch_bounds__(256, 2)
void fused_kernel(const float* __restrict__ x, const float* __restrict__ bias,
                  const float* __restrict__ ce, float4* __restrict__ out) {
    extern __shared__ float smem[];
    float* As = smem;                 // [st][KB][APAD]
    float* Bs = smem + AS_SZ;         // [st][KB][BPAD]

    const int bid = blockIdx.x;
    const int vc  = bid & 15;
    const int b   = bid >> 4;
    const int v0  = vc * VT;

    const int tid  = threadIdx.x;
    const int w    = tid >> 5;
    const int lane = tid & 31;
    const int vl   = lane & 7;            // v = vl*4
    const int dl   = lane >> 3;           // d = w*32 + dl*8
    const int dloc = w * 32 + dl * 8;

    // ---- cp.async address setup (strength-reduced) ----
    // A: threads 0..127, one 16B per chunk: k = tid>>3, q = tid&7
    const float* a_src = x + ((size_t)b * SEQN + (tid >> 3)) * NVV
                         + v0 + (tid & 7) * 4;
    const uint32_t a_dst0 = smem_u32(As) +
        (uint32_t)((((tid >> 3) * APAD) + (tid & 7) * 4) * 4);
    // B: all 256 threads, 4 x 16B per chunk: e = i*256+tid; k=e>>6, q=e&63
    const float* b_src = g_wt + (size_t)(tid >> 6) * DMM + (tid & 63) * 4;
    const uint32_t b_dst0 = smem_u32(Bs) +
        (uint32_t)((((tid >> 6) * BPAD) + (tid & 63) * 4) * 4);
    // per-i increments: e += 256 -> k += 4, row advance 4*DMM / 4*BPAD

    ull c2[4][4];
#pragma unroll
    for (int i = 0; i < 4; ++i)
#pragma unroll
        for (int q = 0; q < 4; ++q) c2[i][q] = 0ull;

    auto issue = [&](int c, int st) {
        const float* asrc = a_src + (size_t)c * KB * NVV;
        const float* bsrc = b_src + (size_t)c * KB * DMM;
        uint32_t ad = a_dst0 + (uint32_t)(st * KB * APAD * 4);
        uint32_t bd = b_dst0 + (uint32_t)(st * KB * BPAD * 4);
        if (tid < 128) CP16(ad, asrc);
#pragma unroll
        for (int i = 0; i < 4; ++i)
            CP16(bd + (uint32_t)(i * 4 * BPAD * 4),
                 bsrc + (size_t)i * 4 * DMM);
        CP_COMMIT();
    };

    issue(0, 0);
    issue(1, 1);

    int st = 0;     // stage of chunk c
    for (int c = 0; c < NCH; ++c) {
        if (c < NCH - 1)
            asm volatile("cp.async.wait_group 1;" ::: "memory");
        else
            asm volatile("cp.async.wait_group 0;" ::: "memory");
        __syncthreads();
        if (c + 2 < NCH) {
            int nst = st + 2; if (nst >= NSTG) nst -= NSTG;
            issue(c + 2, nst);
        }
        const float* ap = As + (size_t)st * KB * APAD + vl * 4;
        const float* bp = Bs + (size_t)st * KB * BPAD + dloc;
#pragma unroll
        for (int k = 0; k < KB; ++k) {
            float4 av = *(const float4*)(ap + k * APAD);
            ulonglong2 b01 = *(const ulonglong2*)(bp + k * BPAD);
            ulonglong2 b23 = *(const ulonglong2*)(bp + k * BPAD + 4);
            ull a0 = pack2(av.x, av.x);
            ull a1 = pack2(av.y, av.y);
            ull a2 = pack2(av.z, av.z);
            ull a3 = pack2(av.w, av.w);
            fma2(c2[0][0], a0, b01.x); fma2(c2[0][1], a0, b01.y);
            fma2(c2[0][2], a0, b23.x); fma2(c2[0][3], a0, b23.y);
            fma2(c2[1][0], a1, b01.x); fma2(c2[1][1], a1, b01.y);
            fma2(c2[1][2], a1, b23.x); fma2(c2[1][3], a1, b23.y);
            fma2(c2[2][0], a2, b01.x); fma2(c2[2][1], a2, b01.y);
            fma2(c2[2][2], a2, b23.x); fma2(c2[2][3], a2, b23.y);
            fma2(c2[3][0], a3, b01.x); fma2(c2[3][1], a3, b01.y);
            fma2(c2[3][2], a3, b23.x); fma2(c2[3][3], a3, b23.y);
        }
        ++st; if (st == NSTG) st = 0;
    }

    // ---- epilogue: cn norm + bias + cosine + sinkhorn ----
    __syncthreads();
    float* cn_s   = smem;                  // [8][256]  = 2048
    float* bias_s = smem + 2048;           // [256]
    float* red    = smem + 2304;           // [8 warps][32 v][9] = 2304
    float* soft_s = smem + 4608;           // [32][8]   = 256
    float* bvals  = smem + 4864;           // [256]

    {   // warp w normalizes cn row w (full 256 d)
        const float* row = ce + w * DMM;
        float s = 0.f;
#pragma unroll
        for (int q = 0; q < DMM / 32; ++q) {
            float t = row[lane + q * 32];
            s += t * t;
        }
#pragma unroll
        for (int o = 16; o; o >>= 1) s += __shfl_xor_sync(0xffffffffu, s, o);
        float nrm = fmaxf(sqrtf(s), 1e-12f);
#pragma unroll
        for (int q = 0; q < DMM / 32; ++q)
            cn_s[w * DMM + lane + q * 32] = row[lane + q * 32] / nrm;
    }
    bias_s[tid] = bias[tid];
    __syncthreads();

#pragma unroll
    for (int vi = 0; vi < 4; ++vi) {      // 4 v per thread
        float y[8];
#pragma unroll
        for (int q = 0; q < 4; ++q) {
            float2 p = unpk2(c2[vi][q]);
            y[2 * q]     = p.x + bias_s[dloc + 2 * q];
            y[2 * q + 1] = p.y + bias_s[dloc + 2 * q + 1];
        }
        float r[9];
        r[0] = 0.f;
#pragma unroll
        for (int q = 0; q < 8; ++q) r[0] += y[q] * y[q];
#pragma unroll
        for (int kk = 0; kk < KCL; ++kk) {
            const float* cp = &cn_s[kk * DMM + dloc];
            float s = 0.f;
#pragma unroll
            for (int q = 0; q < 8; ++q) s += y[q] * cp[q];
            r[1 + kk] = s;
        }
        // reduce across dl (lane bits 3,4)
#pragma unroll
        for (int o = 8; o <= 16; o <<= 1) {
#pragma unroll
            for (int q = 0; q < 9; ++q)
                r[q] += __shfl_xor_sync(0xffffffffu, r[q], o);
        }
        if (dl == 0) {      // lanes 0..7: vl == lane
            float* dst = red + ((size_t)w * VT + lane * 4 + vi) * 9;
#pragma unroll
            for (int q = 0; q < 9; ++q) dst[q] = r[q];
        }
    }
    __syncthreads();

    if (tid < VT) {         // sum across 8 warps -> sinkhorn
        float acc[9];
#pragma unroll
        for (int q = 0; q < 9; ++q) acc[q] = 0.f;
#pragma unroll
        for (int ww = 0; ww < 8; ++ww) {
            const float* src = red + ((size_t)ww * VT + tid) * 9;
#pragma unroll
            for (int q = 0; q < 9; ++q) acc[q] += src[q];
        }
        float nrm = fmaxf(sqrtf(acc[0]), 1e-12f);
        float e[KCL], esum = 0.f;
#pragma unroll
        for (int kk = 0; kk < KCL; ++kk) {
            float prob = acc[1 + kk] / nrm;
            e[kk] = expf(prob / 0.05f);
            esum += e[kk];
        }
#pragma unroll
        for (int kk = 0; kk < KCL; ++kk) soft_s[tid * KCL + kk] = e[kk] / esum;
    }
    __syncthreads();

    {   // bern: one thread per (kk, v) = 8*32 = 256
        int kk = tid >> 5, v = tid & 31;
        int r = kk * (BSZ * NVV) + b * NVV + v0 + v;
        uint32_t bits = threefry_bits32(0u, (uint32_t)r);
        float f = __uint_as_float((bits >> 9) | 0x3f800000u) - 1.0f;
        float u = fmaxf(0.0f, f);
        bvals[tid] = (u < soft_s[v * KCL + kk]) ? 1.0f : 0.0f;
    }
    __syncthreads();

    // ---- write this block's 256 output rows (1 MB) ----
#pragma unroll
    for (int kk = 0; kk < KCL; ++kk) {
        size_t base = (size_t)kk * (BSZ * NVV) + b * NVV + v0;
#pragma unroll
        for (int rr = 0; rr < VT; ++rr) {
            float v = bvals[kk * VT + rr];
            __stcs(&out[(base + rr) * 256 + tid], make_float4(v, v, v, v));
        }
    }
}

// -------- launch -----------------------------------------------------------
extern "C" void kernel_launch(void* const* d_in, const int* in_sizes, int n_in,
                              void* d_out, int out_size) {
    const float* x = nullptr;
    const float* W = nullptr;
    const float* bias = nullptr;
    const float* ce = nullptr;
    for (int i = 0; i < n_in; ++i) {
        switch (in_sizes[i]) {
            case BSZ * SEQN * NVV: x    = (const float*)d_in[i]; break;
            case DMM * SEQN:       W    = (const float*)d_in[i]; break;
            case DMM:              bias = (const float*)d_in[i]; break;
            case KCL * DMM:        ce   = (const float*)d_in[i]; break;
            default: break;
        }
    }
    float4* out = (float4*)d_out;

    static bool attr_set = false;
    if (!attr_set) {
        cudaFuncSetAttribute(fused_kernel,
                             cudaFuncAttributeMaxDynamicSharedMemorySize,
                             SMEM_BYTES);
        attr_set = true;
    }

    transpose_w<<<dim3(SEQN / 32, DMM / 32), 256>>>(W);
    fused_kernel<<<256, 256, SMEM_BYTES>>>(x, bias, ce, out);
    (void)out_size;
}